// round 11
// baseline (speedup 1.0000x reference)
#include <cuda_runtime.h>

#define IS      256
#define TILE    8
#define NTX     (IS / TILE)      // 32 tiles per dim
#define FACES   4096
#define NBATCH  4
#define NEAR_P  0.1f
#define FAR_P   100.0f
#define TINYF   1e-12f
#define EPSV    0.001f
#define BINCAP  256
#define NBINS   (NBATCH * NTX * NTX)   // 4096
#define SLOTS   16                      // max 4x4 tiles per face bbox

typedef unsigned long long u64;

// Per-face precomputed, normalized by det, packed pair-major for f32x2 FMA:
//   g_q0 = (nA0, nA1, nB0, nB1)
//   g_q1 = (nC0, nC1, nA2, P)
//   g_q2 = (nB2, Q,   nC2, R)
//   g_rz = (1/z0, 1/z1, 1/z2, 0)
// n_i(x,y) = nA_i*x + nB_i*y + nC_i (== w_i/det);  inv_zp(x,y) = P*x + Q*y + R
__device__ float4 g_q0[NBATCH * FACES];
__device__ float4 g_q1[NBATCH * FACES];
__device__ float4 g_q2[NBATCH * FACES];
__device__ float4 g_rz[NBATCH * FACES];
__device__ int    g_binCnt[NBINS];          // zero-init at load; raster re-zeros
__device__ int    g_binList[NBINS * BINCAP];

__device__ __forceinline__ u64 fma2(u64 a, u64 b, u64 c)
{
    u64 d;
    asm("fma.rn.f32x2 %0, %1, %2, %3;" : "=l"(d) : "l"(a), "l"(b), "l"(c));
    return d;
}
__device__ __forceinline__ u64 pack2(float lo, float hi)
{
    u64 d;
    asm("mov.b64 %0, {%1, %2};" : "=l"(d) : "f"(lo), "f"(hi));
    return d;
}
__device__ __forceinline__ void unpack2(u64 v, float& lo, float& hi)
{
    asm("mov.b64 {%0, %1}, %2;" : "=f"(lo), "=f"(hi) : "l"(v));
}

// One thread per (face, tile-slot). Slot 0 also writes the packed coeffs.
__global__ __launch_bounds__(256) void setup_kernel(const float* __restrict__ faces)
{
    const int gid  = blockIdx.x * 256 + threadIdx.x;   // 0 .. B*F*SLOTS-1
    const int id   = gid >> 4;                          // face id 0..B*F-1
    const int slot = gid & (SLOTS - 1);
    const int b = id >> 12;
    const int f = id & (FACES - 1);

    const float* fv = faces + (size_t)id * 9;
    const float x0 = fv[0], y0 = fv[1], z0 = fv[2];
    const float x1 = fv[3], y1 = fv[4], z1 = fv[5];
    const float x2 = fv[6], y2 = fv[7], z2 = fv[8];

    const float A0 = y1 - y2, B0 = x2 - x1, C0 = x1 * y2 - x2 * y1;
    const float A1 = y2 - y0, B1 = x0 - x2, C1 = x2 * y0 - x0 * y2;
    const float A2 = y0 - y1, B2 = x1 - x0, C2 = x0 * y1 - x1 * y0;
    const float det = C0 + C1 + C2;      // x/y coeffs cancel: det is constant
    if (!(fabsf(det) > TINYF)) return;   // degenerate: never inside, never binned

    if (slot == 0) {
        // only 1/16 of threads pay the MUFU cost
        const float rd  = 1.0f / det;
        const float rz0 = 1.0f / z0, rz1 = 1.0f / z1, rz2 = 1.0f / z2;
        const float nA0 = A0 * rd, nB0 = B0 * rd, nC0 = C0 * rd;
        const float nA1 = A1 * rd, nB1 = B1 * rd, nC1 = C1 * rd;
        const float nA2 = A2 * rd, nB2 = B2 * rd, nC2 = C2 * rd;
        const float P = nA0 * rz0 + nA1 * rz1 + nA2 * rz2;
        const float Q = nB0 * rz0 + nB1 * rz1 + nB2 * rz2;
        const float R = nC0 * rz0 + nC1 * rz1 + nC2 * rz2;
        g_q0[id] = make_float4(nA0, nA1, nB0, nB1);
        g_q1[id] = make_float4(nC0, nC1, nA2, P);
        g_q2[id] = make_float4(nB2, Q,   nC2, R);
        g_rz[id] = make_float4(rz0, rz1, rz2, 0.0f);
    }

    const float xmn = fminf(x0, fminf(x1, x2)), xmx = fmaxf(x0, fmaxf(x1, x2));
    const float ymn = fminf(y0, fminf(y1, y2)), ymx = fmaxf(y0, fmaxf(y1, y2));

    // pixel center xp = (2*px + 1 - IS)/IS  =>  px = (IS*xp + IS-1)/2 ; widen 1px
    int pxlo = (int)ceilf ((xmn * IS + (IS - 1)) * 0.5f) - 1;
    int pxhi = (int)floorf((xmx * IS + (IS - 1)) * 0.5f) + 1;
    int pylo = (int)ceilf ((ymn * IS + (IS - 1)) * 0.5f) - 1;
    int pyhi = (int)floorf((ymx * IS + (IS - 1)) * 0.5f) + 1;
    pxlo = max(pxlo, 0); pxhi = min(pxhi, IS - 1);
    pylo = max(pylo, 0); pyhi = min(pyhi, IS - 1);
    if (pxlo > pxhi || pylo > pyhi) return;

    const int txlo = pxlo >> 3, txhi = pxhi >> 3;
    const int tylo = pylo >> 3, tyhi = pyhi >> 3;
    const int nx = txhi - txlo + 1;
    const int ny = tyhi - tylo + 1;
    if (slot >= nx * ny) return;

    const int tx = txlo + (slot - (slot / nx) * nx);
    const int ty = tylo + slot / nx;

    // Conservative cull in UNNORMALIZED space (no division):
    const float s = (det > 0.0f) ? 1.0f : -1.0f;
    const float sA0 = s * A0, sB0 = s * B0, sC0 = s * C0;
    const float sA1 = s * A1, sB1 = s * B1, sC1 = s * C1;
    const float sA2 = s * A2, sB2 = s * B2, sC2 = s * C2;

    const float txlo_c = (2.0f * (tx * TILE)            + 1.0f - IS) * (1.0f / IS);
    const float txhi_c = (2.0f * (tx * TILE + TILE - 1) + 1.0f - IS) * (1.0f / IS);
    const float tylo_c = (2.0f * (ty * TILE)            + 1.0f - IS) * (1.0f / IS);
    const float tyhi_c = (2.0f * (ty * TILE + TILE - 1) + 1.0f - IS) * (1.0f / IS);

    const float m0 = fmaxf(sA0 * txlo_c, sA0 * txhi_c) + fmaxf(sB0 * tylo_c, sB0 * tyhi_c) + sC0;
    const float m1 = fmaxf(sA1 * txlo_c, sA1 * txhi_c) + fmaxf(sB1 * tylo_c, sB1 * tyhi_c) + sC1;
    const float m2 = fmaxf(sA2 * txlo_c, sA2 * txhi_c) + fmaxf(sB2 * tylo_c, sB2 * tyhi_c) + sC2;

    const float ad  = fabsf(det);
    const float t0 = -1e-5f * (fabsf(A0) + fabsf(B0)) - 1e-6f * ad;
    const float t1 = -1e-5f * (fabsf(A1) + fabsf(B1)) - 1e-6f * ad;
    const float t2 = -1e-5f * (fabsf(A2) + fabsf(B2)) - 1e-6f * ad;
    if (m0 < t0 || m1 < t1 || m2 < t2) return;   // some edge fully excludes tile

    const int bin = (b * NTX + ty) * NTX + tx;
    const int pos = atomicAdd(&g_binCnt[bin], 1);
    if (pos < BINCAP) g_binList[bin * BINCAP + pos] = f;
}

// 8 warps per CTA. Each warp owns one 8x4 HALF-tile; 1 pixel per lane.
// Inner loop evaluates (n0,n1) and (n2,iz) with packed f32x2 FMAs.
__global__ __launch_bounds__(256) void raster_kernel(
    const float* __restrict__ tex,
    float* __restrict__ out)
{
    __shared__ float4 sq[8][32][3];
    __shared__ int    sidx[8][32];

    const int tid  = threadIdx.x;
    const int warp = tid >> 5;
    const int lane = tid & 31;
    const int b    = blockIdx.z;

    const int tilex = blockIdx.x * 4 + (warp & 3);
    const int tiley = blockIdx.y;
    const int half  = warp >> 2;                       // 0: rows 0-3, 1: rows 4-7

    const int px = tilex * TILE + (lane & 7);
    const int py = tiley * TILE + half * 4 + (lane >> 3);

    const float xp = (2.0f * px + 1.0f - IS) * (1.0f / IS);
    const float yp = (2.0f * py + 1.0f - IS) * (1.0f / IS);
    const u64 xp2 = pack2(xp, xp);
    const u64 yp2 = pack2(yp, yp);

    const int bin = (b * NTX + tiley) * NTX + tilex;
    int n = 0;
    if (lane == 0) n = min(g_binCnt[bin], BINCAP);
    n = __shfl_sync(0xffffffffu, n, 0);
    __syncthreads();                                   // both halves have read the count
    if (half == 0 && lane == 0) g_binCnt[bin] = 0;     // reset for next graph replay

    // Two independent accumulators for ILP. Init 1/FAR subsumes the far clip.
    float biA = 1.0f / FAR_P, biB = 1.0f / FAR_P;
    int   bfA = -1,           bfB = -1;

    for (int start = 0; start < n; start += 32) {
        const int cnt = min(32, n - start);
        if (lane < cnt) {
            const int f  = g_binList[bin * BINCAP + start + lane];
            const int id = b * FACES + f;
            sq[warp][lane][0] = g_q0[id];
            sq[warp][lane][1] = g_q1[id];
            sq[warp][lane][2] = g_q2[id];
            sidx[warp][lane]  = f;
        }
        __syncwarp();

        #pragma unroll 4
        for (int c = 0; c < cnt; c++) {
            const ulonglong2 p0 = *reinterpret_cast<const ulonglong2*>(&sq[warp][c][0]);
            const ulonglong2 p1 = *reinterpret_cast<const ulonglong2*>(&sq[warp][c][1]);
            const ulonglong2 p2 = *reinterpret_cast<const ulonglong2*>(&sq[warp][c][2]);
            // (n0,n1) = xp*(nA0,nA1) + yp*(nB0,nB1) + (nC0,nC1)
            const u64 v01 = fma2(xp2, p0.x, fma2(yp2, p0.y, p1.x));
            // (n2,iz) = xp*(nA2,P) + yp*(nB2,Q) + (nC2,R)
            const u64 v2z = fma2(xp2, p1.y, fma2(yp2, p2.x, p2.y));
            float n0, n1, n2, iz;
            unpack2(v01, n0, n1);
            unpack2(v2z, n2, iz);
            const float mn = fminf(n0, fminf(n1, n2));
            const int f = sidx[warp][c];
            if (c & 1) {
                if (mn > 0.0f && iz < (1.0f / NEAR_P) &&
                    (iz > biB || (iz == biB && f < bfB))) { biB = iz; bfB = f; }
            } else {
                if (mn > 0.0f && iz < (1.0f / NEAR_P) &&
                    (iz > biA || (iz == biA && f < bfA))) { biA = iz; bfA = f; }
            }
        }
        __syncwarp();
    }

    // merge accumulators (order-independent rule: max iz, tie -> min face)
    if (biB > biA || (biB == biA && (unsigned)bfB < (unsigned)bfA)) {
        biA = biB; bfA = bfB;
    }
    const int bestF = bfA;

    // -------- shading from precomputed coefficients --------
    float r = 0.f, g = 0.f, bl = 0.f, alpha = 0.f, depth = FAR_P;
    if (bestF >= 0) {
        const int idw = b * FACES + bestF;
        const float4 q0 = g_q0[idw];
        const float4 q1 = g_q1[idw];
        const float4 q2 = g_q2[idw];
        const float4 rz = g_rz[idw];

        float n0 = fmaf(xp, q0.x, fmaf(yp, q0.z, q1.x));
        float n1 = fmaf(xp, q0.y, fmaf(yp, q0.w, q1.y));
        float n2 = fmaf(xp, q1.z, fmaf(yp, q2.x, q2.z));
        n0 = fminf(fmaxf(n0, 0.f), 1.f);
        n1 = fminf(fmaxf(n1, 0.f), 1.f);
        n2 = fminf(fmaxf(n2, 0.f), 1.f);
        float s = n0 + n1 + n2;
        if (!(s > TINYF)) s = 1.0f;
        const float rs = 1.0f / s;
        const float u0 = n0 * rs * rz.x;
        const float u1 = n1 * rs * rz.y;
        const float u2 = n2 * rs * rz.z;
        float invz = u0 + u1 + u2;
        if (!(fabsf(invz) > TINYF)) invz = 1.0f;
        const float zp = 1.0f / invz;
        depth = zp;
        alpha = 1.0f;

        const float hi = 3.0f - EPSV;   // T-1-EPS, T=4
        const float zp3 = 3.0f * zp;
        const float t0 = fminf(fmaxf(u0 * zp3, 0.f), hi);
        const float t1 = fminf(fmaxf(u1 * zp3, 0.f), hi);
        const float t2 = fminf(fmaxf(u2 * zp3, 0.f), hi);
        const float l0f = floorf(t0), l1f = floorf(t1), l2f = floorf(t2);
        const float f0 = t0 - l0f, f1 = t1 - l1f, f2 = t2 - l2f;
        const int l0 = (int)l0f, l1 = (int)l1f, l2 = (int)l2f;

        const float* tp = tex + (size_t)idw * 192;
        #pragma unroll
        for (int d0 = 0; d0 < 2; d0++) {
            const float wx = d0 ? f0 : 1.0f - f0;
            #pragma unroll
            for (int d1 = 0; d1 < 2; d1++) {
                const float wy = wx * (d1 ? f1 : 1.0f - f1);
                #pragma unroll
                for (int d2 = 0; d2 < 2; d2++) {
                    const float wgt = wy * (d2 ? f2 : 1.0f - f2);
                    const int idx = ((l0 + d0) * 16 + (l1 + d1) * 4 + (l2 + d2)) * 3;
                    r  += wgt * tp[idx + 0];
                    g  += wgt * tp[idx + 1];
                    bl += wgt * tp[idx + 2];
                }
            }
        }
    }
    float* o = out + (((size_t)b * IS + py) * IS + px) * 5;
    o[0] = r; o[1] = g; o[2] = bl; o[3] = alpha; o[4] = depth;
}

extern "C" void kernel_launch(void* const* d_in, const int* in_sizes, int n_in,
                              void* d_out, int out_size)
{
    const float* faces = (const float*)d_in[0];
    const float* tex   = (const float*)d_in[1];
    float* out         = (float*)d_out;

    setup_kernel<<<(NBATCH * FACES * SLOTS) / 256, 256>>>(faces);
    dim3 grid(NTX / 4, NTX, NBATCH);   // 8 x 32 x 4 = 1024 CTAs, 8 half-tiles each
    raster_kernel<<<grid, 256>>>(tex, out);
}

// round 12
// speedup vs baseline: 1.0779x; 1.0779x over previous
#include <cuda_runtime.h>

#define IS      256
#define TILE    8
#define NTX     (IS / TILE)      // 32 tiles per dim
#define FACES   4096
#define NBATCH  4
#define NEAR_P  0.1f
#define FAR_P   100.0f
#define TINYF   1e-12f
#define EPSV    0.001f
#define BINCAP  256
#define NBINS   (NBATCH * NTX * NTX)   // 4096
#define SLOTS   16                      // max 4x4 tiles per face bbox

typedef unsigned long long u64;

// Per-face precomputed, normalized by det, packed pair-major for f32x2 FMA:
//   g_q0 = (nA0, nA1, nB0, nB1)
//   g_q1 = (nC0, nC1, nA2, P)
//   g_q2 = (nB2, Q,   nC2, R)
//   g_rz = (1/z0, 1/z1, 1/z2, 0)
// n_i(x,y) = nA_i*x + nB_i*y + nC_i (== w_i/det);  inv_zp(x,y) = P*x + Q*y + R
__device__ float4 g_q0[NBATCH * FACES];
__device__ float4 g_q1[NBATCH * FACES];
__device__ float4 g_q2[NBATCH * FACES];
__device__ float4 g_rz[NBATCH * FACES];
__device__ int    g_binCnt[NBINS];          // zero-init at load; raster re-zeros
__device__ int    g_binList[NBINS * BINCAP];

__device__ __forceinline__ u64 fma2(u64 a, u64 b, u64 c)
{
    u64 d;
    asm("fma.rn.f32x2 %0, %1, %2, %3;" : "=l"(d) : "l"(a), "l"(b), "l"(c));
    return d;
}
__device__ __forceinline__ u64 pack2(float lo, float hi)
{
    u64 d;
    asm("mov.b64 %0, {%1, %2};" : "=l"(d) : "f"(lo), "f"(hi));
    return d;
}
__device__ __forceinline__ void unpack2(u64 v, float& lo, float& hi)
{
    asm("mov.b64 {%0, %1}, %2;" : "=f"(lo), "=f"(hi) : "l"(v));
}

// One thread per (face, tile-slot). Slot 0 also writes the packed coeffs.
__global__ __launch_bounds__(256) void setup_kernel(const float* __restrict__ faces)
{
    const int gid  = blockIdx.x * 256 + threadIdx.x;   // 0 .. B*F*SLOTS-1
    const int id   = gid >> 4;                          // face id 0..B*F-1
    const int slot = gid & (SLOTS - 1);
    const int b = id >> 12;
    const int f = id & (FACES - 1);

    const float* fv = faces + (size_t)id * 9;
    const float x0 = fv[0], y0 = fv[1], z0 = fv[2];
    const float x1 = fv[3], y1 = fv[4], z1 = fv[5];
    const float x2 = fv[6], y2 = fv[7], z2 = fv[8];

    const float A0 = y1 - y2, B0 = x2 - x1, C0 = x1 * y2 - x2 * y1;
    const float A1 = y2 - y0, B1 = x0 - x2, C1 = x2 * y0 - x0 * y2;
    const float A2 = y0 - y1, B2 = x1 - x0, C2 = x0 * y1 - x1 * y0;
    const float det = C0 + C1 + C2;      // x/y coeffs cancel: det is constant
    if (!(fabsf(det) > TINYF)) return;   // degenerate: never inside, never binned

    if (slot == 0) {
        // only 1/16 of threads pay the MUFU cost
        const float rd  = 1.0f / det;
        const float rz0 = 1.0f / z0, rz1 = 1.0f / z1, rz2 = 1.0f / z2;
        const float nA0 = A0 * rd, nB0 = B0 * rd, nC0 = C0 * rd;
        const float nA1 = A1 * rd, nB1 = B1 * rd, nC1 = C1 * rd;
        const float nA2 = A2 * rd, nB2 = B2 * rd, nC2 = C2 * rd;
        const float P = nA0 * rz0 + nA1 * rz1 + nA2 * rz2;
        const float Q = nB0 * rz0 + nB1 * rz1 + nB2 * rz2;
        const float R = nC0 * rz0 + nC1 * rz1 + nC2 * rz2;
        g_q0[id] = make_float4(nA0, nA1, nB0, nB1);
        g_q1[id] = make_float4(nC0, nC1, nA2, P);
        g_q2[id] = make_float4(nB2, Q,   nC2, R);
        g_rz[id] = make_float4(rz0, rz1, rz2, 0.0f);
    }

    const float xmn = fminf(x0, fminf(x1, x2)), xmx = fmaxf(x0, fmaxf(x1, x2));
    const float ymn = fminf(y0, fminf(y1, y2)), ymx = fmaxf(y0, fmaxf(y1, y2));

    // pixel center xp = (2*px + 1 - IS)/IS  =>  px = (IS*xp + IS-1)/2 ; widen 1px
    int pxlo = (int)ceilf ((xmn * IS + (IS - 1)) * 0.5f) - 1;
    int pxhi = (int)floorf((xmx * IS + (IS - 1)) * 0.5f) + 1;
    int pylo = (int)ceilf ((ymn * IS + (IS - 1)) * 0.5f) - 1;
    int pyhi = (int)floorf((ymx * IS + (IS - 1)) * 0.5f) + 1;
    pxlo = max(pxlo, 0); pxhi = min(pxhi, IS - 1);
    pylo = max(pylo, 0); pyhi = min(pyhi, IS - 1);
    if (pxlo > pxhi || pylo > pyhi) return;

    const int txlo = pxlo >> 3, txhi = pxhi >> 3;
    const int tylo = pylo >> 3, tyhi = pyhi >> 3;
    const int nx = txhi - txlo + 1;
    const int ny = tyhi - tylo + 1;
    if (slot >= nx * ny) return;

    const int tx = txlo + (slot - (slot / nx) * nx);
    const int ty = tylo + slot / nx;

    // Conservative cull in UNNORMALIZED space (no division):
    const float s = (det > 0.0f) ? 1.0f : -1.0f;
    const float sA0 = s * A0, sB0 = s * B0, sC0 = s * C0;
    const float sA1 = s * A1, sB1 = s * B1, sC1 = s * C1;
    const float sA2 = s * A2, sB2 = s * B2, sC2 = s * C2;

    const float txlo_c = (2.0f * (tx * TILE)            + 1.0f - IS) * (1.0f / IS);
    const float txhi_c = (2.0f * (tx * TILE + TILE - 1) + 1.0f - IS) * (1.0f / IS);
    const float tylo_c = (2.0f * (ty * TILE)            + 1.0f - IS) * (1.0f / IS);
    const float tyhi_c = (2.0f * (ty * TILE + TILE - 1) + 1.0f - IS) * (1.0f / IS);

    const float m0 = fmaxf(sA0 * txlo_c, sA0 * txhi_c) + fmaxf(sB0 * tylo_c, sB0 * tyhi_c) + sC0;
    const float m1 = fmaxf(sA1 * txlo_c, sA1 * txhi_c) + fmaxf(sB1 * tylo_c, sB1 * tyhi_c) + sC1;
    const float m2 = fmaxf(sA2 * txlo_c, sA2 * txhi_c) + fmaxf(sB2 * tylo_c, sB2 * tyhi_c) + sC2;

    const float ad  = fabsf(det);
    const float t0 = -1e-5f * (fabsf(A0) + fabsf(B0)) - 1e-6f * ad;
    const float t1 = -1e-5f * (fabsf(A1) + fabsf(B1)) - 1e-6f * ad;
    const float t2 = -1e-5f * (fabsf(A2) + fabsf(B2)) - 1e-6f * ad;
    if (m0 < t0 || m1 < t1 || m2 < t2) return;   // some edge fully excludes tile

    const int bin = (b * NTX + ty) * NTX + tx;
    const int pos = atomicAdd(&g_binCnt[bin], 1);
    if (pos < BINCAP) g_binList[bin * BINCAP + pos] = f;
}

// 8 warps per CTA. Each warp owns one 8x4 HALF-tile; 1 pixel per lane.
// Inner loop evaluates (n0,n1) and (n2,iz) with packed f32x2 FMAs.
__global__ __launch_bounds__(256) void raster_kernel(
    const float* __restrict__ tex,
    float* __restrict__ out)
{
    __shared__ float4 sq[8][32][3];
    __shared__ int    sidx[8][32];

    const int tid  = threadIdx.x;
    const int warp = tid >> 5;
    const int lane = tid & 31;
    const int b    = blockIdx.z;

    const int tilex = blockIdx.x * 4 + (warp & 3);
    const int tiley = blockIdx.y;
    const int half  = warp >> 2;                       // 0: rows 0-3, 1: rows 4-7

    const int px = tilex * TILE + (lane & 7);
    const int py = tiley * TILE + half * 4 + (lane >> 3);

    const float xp = (2.0f * px + 1.0f - IS) * (1.0f / IS);
    const float yp = (2.0f * py + 1.0f - IS) * (1.0f / IS);
    const u64 xp2 = pack2(xp, xp);
    const u64 yp2 = pack2(yp, yp);

    const int bin = (b * NTX + tiley) * NTX + tilex;
    int n = 0;
    if (lane == 0) n = min(g_binCnt[bin], BINCAP);
    n = __shfl_sync(0xffffffffu, n, 0);
    __syncthreads();                                   // both halves have read the count
    if (half == 0 && lane == 0) g_binCnt[bin] = 0;     // reset for next graph replay

    // Two independent accumulators for ILP. Init 1/FAR subsumes the far clip.
    float biA = 1.0f / FAR_P, biB = 1.0f / FAR_P;
    int   bfA = -1,           bfB = -1;

    for (int start = 0; start < n; start += 32) {
        const int cnt = min(32, n - start);
        if (lane < cnt) {
            const int f  = g_binList[bin * BINCAP + start + lane];
            const int id = b * FACES + f;
            sq[warp][lane][0] = g_q0[id];
            sq[warp][lane][1] = g_q1[id];
            sq[warp][lane][2] = g_q2[id];
            sidx[warp][lane]  = f;
        }
        __syncwarp();

        #pragma unroll 4
        for (int c = 0; c < cnt; c++) {
            const ulonglong2 p0 = *reinterpret_cast<const ulonglong2*>(&sq[warp][c][0]);
            const ulonglong2 p1 = *reinterpret_cast<const ulonglong2*>(&sq[warp][c][1]);
            const ulonglong2 p2 = *reinterpret_cast<const ulonglong2*>(&sq[warp][c][2]);
            // (n0,n1) = xp*(nA0,nA1) + yp*(nB0,nB1) + (nC0,nC1)
            const u64 v01 = fma2(xp2, p0.x, fma2(yp2, p0.y, p1.x));
            // (n2,iz) = xp*(nA2,P) + yp*(nB2,Q) + (nC2,R)
            const u64 v2z = fma2(xp2, p1.y, fma2(yp2, p2.x, p2.y));
            float n0, n1, n2, iz;
            unpack2(v01, n0, n1);
            unpack2(v2z, n2, iz);
            const float mn = fminf(n0, fminf(n1, n2));
            const int f = sidx[warp][c];
            if (c & 1) {
                if (mn > 0.0f && iz < (1.0f / NEAR_P) &&
                    (iz > biB || (iz == biB && f < bfB))) { biB = iz; bfB = f; }
            } else {
                if (mn > 0.0f && iz < (1.0f / NEAR_P) &&
                    (iz > biA || (iz == biA && f < bfA))) { biA = iz; bfA = f; }
            }
        }
        __syncwarp();
    }

    // merge accumulators (order-independent rule: max iz, tie -> min face)
    if (biB > biA || (biB == biA && (unsigned)bfB < (unsigned)bfA)) {
        biA = biB; bfA = bfB;
    }
    const int bestF = bfA;

    // -------- shading from precomputed coefficients --------
    float r = 0.f, g = 0.f, bl = 0.f, alpha = 0.f, depth = FAR_P;
    if (bestF >= 0) {
        const int idw = b * FACES + bestF;
        const float4 q0 = g_q0[idw];
        const float4 q1 = g_q1[idw];
        const float4 q2 = g_q2[idw];
        const float4 rz = g_rz[idw];

        float n0 = fmaf(xp, q0.x, fmaf(yp, q0.z, q1.x));
        float n1 = fmaf(xp, q0.y, fmaf(yp, q0.w, q1.y));
        float n2 = fmaf(xp, q1.z, fmaf(yp, q2.x, q2.z));
        n0 = fminf(fmaxf(n0, 0.f), 1.f);
        n1 = fminf(fmaxf(n1, 0.f), 1.f);
        n2 = fminf(fmaxf(n2, 0.f), 1.f);
        float s = n0 + n1 + n2;
        if (!(s > TINYF)) s = 1.0f;
        const float rs = 1.0f / s;
        const float u0 = n0 * rs * rz.x;
        const float u1 = n1 * rs * rz.y;
        const float u2 = n2 * rs * rz.z;
        float invz = u0 + u1 + u2;
        if (!(fabsf(invz) > TINYF)) invz = 1.0f;
        const float zp = 1.0f / invz;
        depth = zp;
        alpha = 1.0f;

        const float hi = 3.0f - EPSV;   // T-1-EPS, T=4
        const float zp3 = 3.0f * zp;
        const float t0 = fminf(fmaxf(u0 * zp3, 0.f), hi);
        const float t1 = fminf(fmaxf(u1 * zp3, 0.f), hi);
        const float t2 = fminf(fmaxf(u2 * zp3, 0.f), hi);
        const float l0f = floorf(t0), l1f = floorf(t1), l2f = floorf(t2);
        const float f0 = t0 - l0f, f1 = t1 - l1f, f2 = t2 - l2f;
        const int l0 = (int)l0f, l1 = (int)l1f, l2 = (int)l2f;

        const float* tp = tex + (size_t)idw * 192;
        #pragma unroll
        for (int d0 = 0; d0 < 2; d0++) {
            const float wx = d0 ? f0 : 1.0f - f0;
            #pragma unroll
            for (int d1 = 0; d1 < 2; d1++) {
                const float wy = wx * (d1 ? f1 : 1.0f - f1);
                #pragma unroll
                for (int d2 = 0; d2 < 2; d2++) {
                    const float wgt = wy * (d2 ? f2 : 1.0f - f2);
                    const int idx = ((l0 + d0) * 16 + (l1 + d1) * 4 + (l2 + d2)) * 3;
                    r  += wgt * tp[idx + 0];
                    g  += wgt * tp[idx + 1];
                    bl += wgt * tp[idx + 2];
                }
            }
        }
    }
    float* o = out + (((size_t)b * IS + py) * IS + px) * 5;
    o[0] = r; o[1] = g; o[2] = bl; o[3] = alpha; o[4] = depth;
}

extern "C" void kernel_launch(void* const* d_in, const int* in_sizes, int n_in,
                              void* d_out, int out_size)
{
    const float* faces = (const float*)d_in[0];
    const float* tex   = (const float*)d_in[1];
    float* out         = (float*)d_out;

    setup_kernel<<<(NBATCH * FACES * SLOTS) / 256, 256>>>(faces);
    dim3 grid(NTX / 4, NTX, NBATCH);   // 8 x 32 x 4 = 1024 CTAs, 8 half-tiles each
    raster_kernel<<<grid, 256>>>(tex, out);
}